// round 12
// baseline (speedup 1.0000x reference)
#include <cuda_runtime.h>
#include <cstdint>

#define BB 4
#define LL 2048
#define DD 1024
#define HH 16
#define HDIM 64

// Scratch (allocation-free rule: __device__ globals). 4 x 32 MB.
__device__ float g_Q[BB*LL*DD];
__device__ float g_K[BB*LL*DD];
__device__ float g_V[BB*LL*DD];
__device__ float g_C[BB*LL*DD];

__device__ __forceinline__ uint32_t f2tf32(float x) {
    uint32_t u;
    asm("cvt.rna.tf32.f32 %0, %1;" : "=r"(u) : "f"(x));
    return u;
}

__device__ __forceinline__ void mma_tf32(float* c,
    uint32_t a0, uint32_t a1, uint32_t a2, uint32_t a3,
    uint32_t b0, uint32_t b1)
{
    asm volatile(
        "mma.sync.aligned.m16n8k8.row.col.f32.tf32.tf32.f32 "
        "{%0,%1,%2,%3}, {%4,%5,%6,%7}, {%8,%9}, {%0,%1,%2,%3};\n"
        : "+f"(c[0]), "+f"(c[1]), "+f"(c[2]), "+f"(c[3])
        : "r"(a0), "r"(a1), "r"(a2), "r"(a3), "r"(b0), "r"(b1));
}

__device__ __forceinline__ void cpasync16(uint32_t dst, const void* src) {
    asm volatile("cp.async.cg.shared.global [%0], [%1], 16;\n"
                 :: "r"(dst), "l"(src));
}
__device__ __forceinline__ void cp_commit() {
    asm volatile("cp.async.commit_group;\n" ::: "memory");
}
__device__ __forceinline__ void cp_wait1() {
    asm volatile("cp.async.wait_group 1;\n" ::: "memory");
}

// ---------------------------------------------------------------------------
// TF32 tensor-core GEMM, 3-stage cp.async pipeline, one sync per k-iter.
// C[M,N] = A[M,K] @ W[K,N] + bias[N], 128x128x32 tile, 8 warps, 64x32/warp.
// ---------------------------------------------------------------------------
#define GBM 128
#define GBN 128
#define GBK 32
#define AP 36
#define BP 136
#define GSTAGE (GBM*AP + GBK*BP)            // words per stage
#define GSMEM (3 * GSTAGE * 4)              // 107520 B

struct GemmArgs {
    const float* A; const float* W; const float* bias; float* C;
};

__global__ __launch_bounds__(256) void sgemm_tf32_pipe_kernel(
    GemmArgs ga0, GemmArgs ga1, GemmArgs ga2, int M, int N, int K)
{
    extern __shared__ float smemf[];
    // stage s: A at smemf + s*GSTAGE, B at smemf + s*GSTAGE + GBM*AP

    GemmArgs ga = (blockIdx.z == 0) ? ga0 : (blockIdx.z == 1) ? ga1 : ga2;
    const float* __restrict__ A    = ga.A;
    const float* __restrict__ W    = ga.W;
    const float* __restrict__ bias = ga.bias;
    float* __restrict__ C          = ga.C;

    int tid  = threadIdx.x;
    int row0 = blockIdx.y * GBM;
    int col0 = blockIdx.x * GBN;

    int lane = tid & 31;
    int wid  = tid >> 5;
    int g    = lane >> 2;
    int tg   = lane & 3;
    int wm0  = (wid >> 2) * 64;
    int wn0  = (wid & 3) * 32;

    int arow = tid >> 3;          // 0..31 (+32*it)
    int acol = (tid & 7) << 2;    // 0..28
    int brow = tid >> 5;          // 0..7  (+8*it)
    int bcol = (tid & 31) << 2;   // 0..124

    uint32_t sS = (uint32_t)__cvta_generic_to_shared(smemf);

    const float* Abase = A + (long)(row0 + arow) * K + acol;
    const float* Wbase = W + (long)brow * N + col0 + bcol;

    float acc[4][4][4];
#pragma unroll
    for (int i = 0; i < 4; i++)
#pragma unroll
        for (int j = 0; j < 4; j++)
#pragma unroll
            for (int c = 0; c < 4; c++) acc[i][j][c] = 0.f;

    const int NIT = 1024 / GBK;  // 32

    uint32_t adoff = (uint32_t)(arow * AP + acol) * 4u;
    uint32_t bdoff = (uint32_t)(GBM * AP + brow * BP + bcol) * 4u;

    // prologue: stages 0 and 1
#pragma unroll
    for (int p = 0; p < 2; p++) {
        uint32_t base = sS + (uint32_t)(p * GSTAGE) * 4u;
        int k0 = p * GBK;
#pragma unroll
        for (int it = 0; it < 4; it++)
            cpasync16(base + adoff + it * 32 * AP * 4, Abase + (long)(32 * it) * K + k0);
#pragma unroll
        for (int it = 0; it < 4; it++)
            cpasync16(base + bdoff + it * 8 * BP * 4, Wbase + (long)(k0 + 8 * it) * N);
        cp_commit();
    }

    int buf = 0, nbuf = 2;
    for (int itk = 0; itk < NIT; itk++) {
        cp_wait1();            // stage itk resident
        __syncthreads();       // all warps past compute(itk-1); buf nbuf free

        if (itk + 2 < NIT) {
            uint32_t base = sS + (uint32_t)(nbuf * GSTAGE) * 4u;
            int k0 = (itk + 2) * GBK;
#pragma unroll
            for (int it = 0; it < 4; it++)
                cpasync16(base + adoff + it * 32 * AP * 4, Abase + (long)(32 * it) * K + k0);
#pragma unroll
            for (int it = 0; it < 4; it++)
                cpasync16(base + bdoff + it * 8 * BP * 4, Wbase + (long)(k0 + 8 * it) * N);
        }
        cp_commit();

        const float* Ab = smemf + buf * GSTAGE;
        const float* Bb = Ab + GBM * AP;

#pragma unroll
        for (int ks = 0; ks < GBK; ks += 8) {
            uint32_t af[4][4], bf[4][2];
#pragma unroll
            for (int i = 0; i < 4; i++) {
                int m = wm0 + 16 * i;
                af[i][0] = f2tf32(Ab[(m + g)     * AP + ks + tg]);
                af[i][1] = f2tf32(Ab[(m + g + 8) * AP + ks + tg]);
                af[i][2] = f2tf32(Ab[(m + g)     * AP + ks + tg + 4]);
                af[i][3] = f2tf32(Ab[(m + g + 8) * AP + ks + tg + 4]);
            }
#pragma unroll
            for (int j = 0; j < 4; j++) {
                int n = wn0 + 8 * j;
                bf[j][0] = f2tf32(Bb[(ks + tg)     * BP + n + g]);
                bf[j][1] = f2tf32(Bb[(ks + tg + 4) * BP + n + g]);
            }
#pragma unroll
            for (int i = 0; i < 4; i++)
#pragma unroll
                for (int j = 0; j < 4; j++)
                    mma_tf32(acc[i][j], af[i][0], af[i][1], af[i][2], af[i][3],
                             bf[j][0], bf[j][1]);
        }

        buf = (buf + 1) % 3;
        nbuf = (nbuf + 1) % 3;
    }

    // Epilogue
#pragma unroll
    for (int i = 0; i < 4; i++) {
        int r = row0 + wm0 + 16 * i + g;
#pragma unroll
        for (int j = 0; j < 4; j++) {
            int c = col0 + wn0 + 8 * j + 2 * tg;
            float b0 = bias[c], b1 = bias[c + 1];
            float2 o0 = make_float2(acc[i][j][0] + b0, acc[i][j][1] + b1);
            float2 o1 = make_float2(acc[i][j][2] + b0, acc[i][j][3] + b1);
            *(float2*)&C[(long)r * N + c]       = o0;
            *(float2*)&C[(long)(r + 8) * N + c] = o1;
        }
    }
}

// ---------------------------------------------------------------------------
// TF32 tensor-core flash attention, v2:
//  - Q/K stored column-PERMUTED (col c -> slot ((c&3)<<1)|(c>>2) in 8-groups)
//    so each A/B fragment pair is one LDS.64.
//  - V stored TRANSPOSED [hd][key] with the same perm on the key dim.
//  - mask read directly from gmem (int2 per thread), no smem staging.
//  - 2 __syncthreads per iter + __syncwarp for warp-local P.
// ---------------------------------------------------------------------------
#define AQ 128
#define AK 64
#define QSTR 68
#define KSTR 68
#define VSTR 68
#define PSTR 68
#define ATT_SMEM ((AQ*QSTR + AK*KSTR + HDIM*VSTR + AQ*PSTR) * 4)

__global__ __launch_bounds__(256) void attn_tf32_kernel(
    const float* __restrict__ Qp, const float* __restrict__ Kp,
    const float* __restrict__ Vp, const int* __restrict__ mask,
    float* __restrict__ Ctx)
{
    extern __shared__ char smemraw[];
    uint32_t* Qs = (uint32_t*)smemraw;           // [AQ][QSTR] tf32, col-perm
    uint32_t* Ks = Qs + AQ * QSTR;               // [AK][KSTR] tf32, col-perm
    uint32_t* Vt = Ks + AK * KSTR;               // [HDIM][VSTR] tf32, transposed+perm
    uint32_t* Pu = Vt + HDIM * VSTR;             // [AQ][PSTR] P tf32 bits

    int tid  = threadIdx.x;
    int lane = tid & 31, wid = tid >> 5;
    int g = lane >> 2, tg = lane & 3;
    int wm = wid * 16;
    int bh = blockIdx.y;
    int b = bh / HH, h = bh % HH;
    int q0 = blockIdx.x * AQ;

    int row0 = wm + g;
    int row1 = wm + g + 8;

    // Stage Q once (scale folded; col-perm layout)
    const float* Qbase = Qp + ((long)(b * LL + q0)) * DD + h * HDIM;
#pragma unroll
    for (int it = 0; it < 8; it++) {
        int s = tid + it * 256;
        int r = s >> 4, c4 = (s & 15) << 2;
        float4 qv = *(const float4*)(Qbase + (long)r * DD + c4);
        int base = r * QSTR + (c4 & ~7) + ((c4 >> 2) & 1);
        Qs[base + 0] = f2tf32(qv.x * 0.125f);
        Qs[base + 2] = f2tf32(qv.y * 0.125f);
        Qs[base + 4] = f2tf32(qv.z * 0.125f);
        Qs[base + 6] = f2tf32(qv.w * 0.125f);
    }

    float Of[8][4];
#pragma unroll
    for (int j = 0; j < 8; j++)
#pragma unroll
        for (int c = 0; c < 4; c++) Of[j][c] = 0.f;
    float m0 = -1e30f, m1 = -1e30f, l0 = 0.f, l1 = 0.f;

    const float* Kb = Kp + ((long)(b * LL)) * DD + h * HDIM;
    const float* Vb = Vp + ((long)(b * LL)) * DD + h * HDIM;
    const int*   Mr0 = mask + (long)b * LL * LL + (long)(q0 + row0) * LL;
    const int*   Mr1 = mask + (long)b * LL * LL + (long)(q0 + row1) * LL;

    for (int kt = 0; kt < LL; kt += AK) {
        __syncthreads();  // all warps done with prev Ks (S) and Vt (PV) reads

        // Stage K (col-perm) and V (transposed + perm on key dim)
#pragma unroll
        for (int it = 0; it < 4; it++) {
            int s = tid + it * 256;
            int r = s >> 4, c4 = (s & 15) << 2;
            float4 kv = *(const float4*)(Kb + (long)(kt + r) * DD + c4);
            int kbase = r * KSTR + (c4 & ~7) + ((c4 >> 2) & 1);
            Ks[kbase + 0] = f2tf32(kv.x);
            Ks[kbase + 2] = f2tf32(kv.y);
            Ks[kbase + 4] = f2tf32(kv.z);
            Ks[kbase + 6] = f2tf32(kv.w);
            float4 vv = *(const float4*)(Vb + (long)(kt + r) * DD + c4);
            int rslot = (r & ~7) + (((r & 3) << 1) | ((r >> 2) & 1));
            Vt[(c4 + 0) * VSTR + rslot] = f2tf32(vv.x);
            Vt[(c4 + 1) * VSTR + rslot] = f2tf32(vv.y);
            Vt[(c4 + 2) * VSTR + rslot] = f2tf32(vv.z);
            Vt[(c4 + 3) * VSTR + rslot] = f2tf32(vv.w);
        }
        __syncthreads();

        // S = Q @ K^T
        float sf[8][4];
#pragma unroll
        for (int j = 0; j < 8; j++)
#pragma unroll
            for (int c = 0; c < 4; c++) sf[j][c] = 0.f;

#pragma unroll
        for (int kg = 0; kg < 8; kg++) {
            uint2 qa = *(const uint2*)&Qs[row0 * QSTR + 8 * kg + 2 * tg];
            uint2 qb = *(const uint2*)&Qs[row1 * QSTR + 8 * kg + 2 * tg];
#pragma unroll
            for (int j = 0; j < 8; j++) {
                uint2 kb = *(const uint2*)&Ks[(8 * j + g) * KSTR + 8 * kg + 2 * tg];
                mma_tf32(sf[j], qa.x, qb.x, qa.y, qb.y, kb.x, kb.y);
            }
        }

        // Mask (direct gmem) + online softmax
        float mx0 = -1e30f, mx1 = -1e30f;
#pragma unroll
        for (int j = 0; j < 8; j++) {
            int cb = kt + 8 * j + 2 * tg;
            int2 mv0 = *(const int2*)(Mr0 + cb);
            int2 mv1 = *(const int2*)(Mr1 + cb);
            sf[j][0] = mv0.x ? sf[j][0] : -1e30f;
            sf[j][1] = mv0.y ? sf[j][1] : -1e30f;
            sf[j][2] = mv1.x ? sf[j][2] : -1e30f;
            sf[j][3] = mv1.y ? sf[j][3] : -1e30f;
            mx0 = fmaxf(mx0, fmaxf(sf[j][0], sf[j][1]));
            mx1 = fmaxf(mx1, fmaxf(sf[j][2], sf[j][3]));
        }
        mx0 = fmaxf(mx0, __shfl_xor_sync(0xffffffffu, mx0, 1));
        mx0 = fmaxf(mx0, __shfl_xor_sync(0xffffffffu, mx0, 2));
        mx1 = fmaxf(mx1, __shfl_xor_sync(0xffffffffu, mx1, 1));
        mx1 = fmaxf(mx1, __shfl_xor_sync(0xffffffffu, mx1, 2));

        float mn0 = fmaxf(m0, mx0), mn1 = fmaxf(m1, mx1);
        float cr0 = __expf(m0 - mn0), cr1 = __expf(m1 - mn1);
        m0 = mn0; m1 = mn1;

        float ls0 = 0.f, ls1 = 0.f;
#pragma unroll
        for (int j = 0; j < 8; j++) {
            float p0 = __expf(sf[j][0] - mn0);
            float p1 = __expf(sf[j][1] - mn0);
            float p2 = __expf(sf[j][2] - mn1);
            float p3 = __expf(sf[j][3] - mn1);
            ls0 += p0 + p1;
            ls1 += p2 + p3;
            int cb = 8 * j + 2 * tg;
            *(uint2*)&Pu[row0 * PSTR + cb] = make_uint2(f2tf32(p0), f2tf32(p1));
            *(uint2*)&Pu[row1 * PSTR + cb] = make_uint2(f2tf32(p2), f2tf32(p3));
        }
        ls0 += __shfl_xor_sync(0xffffffffu, ls0, 1);
        ls0 += __shfl_xor_sync(0xffffffffu, ls0, 2);
        ls1 += __shfl_xor_sync(0xffffffffu, ls1, 1);
        ls1 += __shfl_xor_sync(0xffffffffu, ls1, 2);
        l0 = l0 * cr0 + ls0;
        l1 = l1 * cr1 + ls1;
#pragma unroll
        for (int j = 0; j < 8; j++) {
            Of[j][0] *= cr0; Of[j][1] *= cr0;
            Of[j][2] *= cr1; Of[j][3] *= cr1;
        }
        __syncwarp();  // P rows are warp-local; lane-cross visibility only

        // O += P @ V  (V transposed+perm: one LDS.64 per B-fragment pair)
#pragma unroll
        for (int kg = 0; kg < 8; kg++) {
            int ks = 8 * kg;
            uint32_t a0 = Pu[row0 * PSTR + ks + tg];
            uint32_t a1 = Pu[row1 * PSTR + ks + tg];
            uint32_t a2 = Pu[row0 * PSTR + ks + tg + 4];
            uint32_t a3 = Pu[row1 * PSTR + ks + tg + 4];
#pragma unroll
            for (int j = 0; j < 8; j++) {
                uint2 vb = *(const uint2*)&Vt[(8 * j + g) * VSTR + ks + 2 * tg];
                mma_tf32(Of[j], a0, a1, a2, a3, vb.x, vb.y);
            }
        }
    }

    float inv0 = 1.f / l0, inv1 = 1.f / l1;
    float* Ob = Ctx + ((long)(b * LL + q0)) * DD + h * HDIM;
#pragma unroll
    for (int j = 0; j < 8; j++) {
        int c = 8 * j + 2 * tg;
        *(float2*)&Ob[(long)row0 * DD + c] =
            make_float2(Of[j][0] * inv0, Of[j][1] * inv0);
        *(float2*)&Ob[(long)row1 * DD + c] =
            make_float2(Of[j][2] * inv1, Of[j][3] * inv1);
    }
}

// ---------------------------------------------------------------------------
extern "C" void kernel_launch(void* const* d_in, const int* in_sizes, int n_in,
                              void* d_out, int out_size)
{
    const float* q    = (const float*)d_in[0];
    const float* k    = (const float*)d_in[1];
    const float* v    = (const float*)d_in[2];
    const int*   mask = (const int*)  d_in[3];
    const float* WQ   = (const float*)d_in[4];
    const float* bQ   = (const float*)d_in[5];
    const float* WK   = (const float*)d_in[6];
    const float* bK   = (const float*)d_in[7];
    const float* WV   = (const float*)d_in[8];
    const float* bV   = (const float*)d_in[9];
    const float* WO   = (const float*)d_in[10];
    const float* bO   = (const float*)d_in[11];
    float* out = (float*)d_out;

    float *gQ, *gK, *gV, *gC;
    cudaGetSymbolAddress((void**)&gQ, g_Q);
    cudaGetSymbolAddress((void**)&gK, g_K);
    cudaGetSymbolAddress((void**)&gV, g_V);
    cudaGetSymbolAddress((void**)&gC, g_C);

    static int attr_set = 0;
    if (!attr_set) {
        cudaFuncSetAttribute(sgemm_tf32_pipe_kernel,
                             cudaFuncAttributeMaxDynamicSharedMemorySize, GSMEM);
        cudaFuncSetAttribute(attn_tf32_kernel,
                             cudaFuncAttributeMaxDynamicSharedMemorySize, ATT_SMEM);
        attr_set = 1;
    }

    const int M = BB * LL;  // 8192

    GemmArgs gq = {q, WQ, bQ, gQ};
    GemmArgs gk = {k, WK, bK, gK};
    GemmArgs gv = {v, WV, bV, gV};

    sgemm_tf32_pipe_kernel<<<dim3(DD / GBN, M / GBM, 3), 256, GSMEM>>>(
        gq, gk, gv, M, DD, DD);

    attn_tf32_kernel<<<dim3(LL / AQ, BB * HH), 256, ATT_SMEM>>>(
        gQ, gK, gV, mask, gC);

    GemmArgs go = {gC, WO, bO, out};
    sgemm_tf32_pipe_kernel<<<dim3(DD / GBN, M / GBM, 1), 256, GSMEM>>>(
        go, go, go, M, DD, DD);
}

// round 13
// speedup vs baseline: 1.3449x; 1.3449x over previous
#include <cuda_runtime.h>
#include <cstdint>

#define BB 4
#define LL 2048
#define DD 1024
#define HH 16
#define HDIM 64

// Scratch (allocation-free rule: __device__ globals). 4 x 32 MB.
__device__ float g_Q[BB*LL*DD];
__device__ float g_K[BB*LL*DD];
__device__ float g_V[BB*LL*DD];
__device__ float g_C[BB*LL*DD];

__device__ __forceinline__ uint32_t f2tf32(float x) {
    uint32_t u;
    asm("cvt.rna.tf32.f32 %0, %1;" : "=r"(u) : "f"(x));
    return u;
}

__device__ __forceinline__ void mma_tf32(float* c,
    uint32_t a0, uint32_t a1, uint32_t a2, uint32_t a3,
    uint32_t b0, uint32_t b1)
{
    asm volatile(
        "mma.sync.aligned.m16n8k8.row.col.f32.tf32.tf32.f32 "
        "{%0,%1,%2,%3}, {%4,%5,%6,%7}, {%8,%9}, {%0,%1,%2,%3};\n"
        : "+f"(c[0]), "+f"(c[1]), "+f"(c[2]), "+f"(c[3])
        : "r"(a0), "r"(a1), "r"(a2), "r"(a3), "r"(b0), "r"(b1));
}

__device__ __forceinline__ void cpasync16(uint32_t dst, const void* src) {
    asm volatile("cp.async.cg.shared.global [%0], [%1], 16;\n"
                 :: "r"(dst), "l"(src));
}
__device__ __forceinline__ void cp_commit() {
    asm volatile("cp.async.commit_group;\n" ::: "memory");
}
__device__ __forceinline__ void cp_wait1() {
    asm volatile("cp.async.wait_group 1;\n" ::: "memory");
}

// ---------------------------------------------------------------------------
// TF32 tensor-core GEMM with 2-stage cp.async pipeline (R10 version, 339us).
// C[M,N] = A[M,K] @ W[K,N] + bias[N], 128x128x32 tile, 8 warps, 64x32/warp.
// ---------------------------------------------------------------------------
#define GBM 128
#define GBN 128
#define GBK 32
#define AP 36
#define BP 136
#define GSMEM ((2*GBM*AP + 2*GBK*BP) * 4)   // 71680 B

struct GemmArgs {
    const float* A; const float* W; const float* bias; float* C;
};

__global__ __launch_bounds__(256) void sgemm_tf32_pipe_kernel(
    GemmArgs ga0, GemmArgs ga1, GemmArgs ga2, int M, int N, int K)
{
    extern __shared__ float smemf[];
    float* Asf = smemf;                 // [2][128][AP]
    float* Bsf = smemf + 2 * GBM * AP;  // [2][32][BP]

    GemmArgs ga = (blockIdx.z == 0) ? ga0 : (blockIdx.z == 1) ? ga1 : ga2;
    const float* __restrict__ A    = ga.A;
    const float* __restrict__ W    = ga.W;
    const float* __restrict__ bias = ga.bias;
    float* __restrict__ C          = ga.C;

    int tid  = threadIdx.x;
    int row0 = blockIdx.y * GBM;
    int col0 = blockIdx.x * GBN;

    int lane = tid & 31;
    int wid  = tid >> 5;
    int g    = lane >> 2;
    int tg   = lane & 3;
    int wm0  = (wid >> 2) * 64;
    int wn0  = (wid & 3) * 32;

    int arow = tid >> 3;          // 0..31 (+32*it)
    int acol = (tid & 7) << 2;    // 0..28
    int brow = tid >> 5;          // 0..7  (+8*it)
    int bcol = (tid & 31) << 2;   // 0..124

    uint32_t aS = (uint32_t)__cvta_generic_to_shared(Asf);
    uint32_t bS = (uint32_t)__cvta_generic_to_shared(Bsf);

    const float* Abase = A + (long)(row0 + arow) * K + acol;
    const float* Wbase = W + (long)brow * N + col0 + bcol;

    float acc[4][4][4];
#pragma unroll
    for (int i = 0; i < 4; i++)
#pragma unroll
        for (int j = 0; j < 4; j++)
#pragma unroll
            for (int c = 0; c < 4; c++) acc[i][j][c] = 0.f;

    const int NIT = 1024 / GBK;  // 32

    // prologue: stage tile 0 into buf 0
    {
        uint32_t ad = aS + (uint32_t)(arow * AP + acol) * 4u;
        uint32_t bd = bS + (uint32_t)(brow * BP + bcol) * 4u;
#pragma unroll
        for (int it = 0; it < 4; it++)
            cpasync16(ad + it * 32 * AP * 4, Abase + (long)(32 * it) * K);
#pragma unroll
        for (int it = 0; it < 4; it++)
            cpasync16(bd + it * 8 * BP * 4, Wbase + (long)(8 * it) * N);
        cp_commit();
    }

    for (int itk = 0; itk < NIT; itk++) {
        int buf = itk & 1;
        if (itk + 1 < NIT) {
            int k0n = (itk + 1) * GBK;
            uint32_t ad = aS + (uint32_t)(((buf ^ 1) * GBM + arow) * AP + acol) * 4u;
            uint32_t bd = bS + (uint32_t)(((buf ^ 1) * GBK + brow) * BP + bcol) * 4u;
#pragma unroll
            for (int it = 0; it < 4; it++)
                cpasync16(ad + it * 32 * AP * 4, Abase + (long)(32 * it) * K + k0n);
#pragma unroll
            for (int it = 0; it < 4; it++)
                cpasync16(bd + it * 8 * BP * 4, Wbase + (long)(k0n + 8 * it) * N);
        }
        cp_commit();
        cp_wait1();
        __syncthreads();

        const float* Ab = Asf + buf * GBM * AP;
        const float* Bb = Bsf + buf * GBK * BP;

#pragma unroll
        for (int ks = 0; ks < GBK; ks += 8) {
            uint32_t af[4][4], bf[4][2];
#pragma unroll
            for (int i = 0; i < 4; i++) {
                int m = wm0 + 16 * i;
                af[i][0] = f2tf32(Ab[(m + g)     * AP + ks + tg]);
                af[i][1] = f2tf32(Ab[(m + g + 8) * AP + ks + tg]);
                af[i][2] = f2tf32(Ab[(m + g)     * AP + ks + tg + 4]);
                af[i][3] = f2tf32(Ab[(m + g + 8) * AP + ks + tg + 4]);
            }
#pragma unroll
            for (int j = 0; j < 4; j++) {
                int n = wn0 + 8 * j;
                bf[j][0] = f2tf32(Bb[(ks + tg)     * BP + n + g]);
                bf[j][1] = f2tf32(Bb[(ks + tg + 4) * BP + n + g]);
            }
#pragma unroll
            for (int i = 0; i < 4; i++)
#pragma unroll
                for (int j = 0; j < 4; j++)
                    mma_tf32(acc[i][j], af[i][0], af[i][1], af[i][2], af[i][3],
                             bf[j][0], bf[j][1]);
        }
        __syncthreads();
    }

    // Epilogue
#pragma unroll
    for (int i = 0; i < 4; i++) {
        int r = row0 + wm0 + 16 * i + g;
#pragma unroll
        for (int j = 0; j < 4; j++) {
            int c = col0 + wn0 + 8 * j + 2 * tg;
            float b0 = bias[c], b1 = bias[c + 1];
            float2 o0 = make_float2(acc[i][j][0] + b0, acc[i][j][1] + b1);
            float2 o1 = make_float2(acc[i][j][2] + b0, acc[i][j][3] + b1);
            *(float2*)&C[(long)r * N + c]       = o0;
            *(float2*)&C[(long)(r + 8) * N + c] = o1;
        }
    }
}

// ---------------------------------------------------------------------------
// TF32 tensor-core flash attention (R9/R10 v1 layouts) + mask-as-bytes +
// warp-local P sync. One block = one (b,h) x 128-query tile; 8 warps,
// warp w owns rows [16w,16w+16); TK=64 key tile.
// ---------------------------------------------------------------------------
#define AQ 128
#define AK 64
#define QSTR 68
#define KSTR 68
#define VSTR 72
#define PSTR 68
#define MSTRB 68   // mask byte-row stride (17 words -> conflict-free)
#define ATT_SMEM ((AQ*QSTR + AK*KSTR + AK*VSTR + AQ*PSTR) * 4 + AQ*MSTRB)

__global__ __launch_bounds__(256) void attn_tf32_kernel(
    const float* __restrict__ Qp, const float* __restrict__ Kp,
    const float* __restrict__ Vp, const int* __restrict__ mask,
    float* __restrict__ Ctx)
{
    extern __shared__ char smemraw[];
    uint32_t* Qs = (uint32_t*)smemraw;           // [AQ][QSTR] tf32
    uint32_t* Ks = Qs + AQ * QSTR;               // [AK][KSTR] tf32
    uint32_t* Vs = Ks + AK * KSTR;               // [AK][VSTR] tf32
    uint32_t* Pu = Vs + AK * VSTR;               // [AQ][PSTR] P tf32 bits
    unsigned char* Ms = (unsigned char*)(Pu + AQ * PSTR);  // [AQ][MSTRB] mask bytes

    int tid  = threadIdx.x;
    int lane = tid & 31, wid = tid >> 5;
    int g = lane >> 2, tg = lane & 3;
    int wm = wid * 16;
    int bh = blockIdx.y;
    int b = bh / HH, h = bh % HH;
    int q0 = blockIdx.x * AQ;

    int row0 = wm + g;
    int row1 = wm + g + 8;

    // Stage Q once (scale 0.125 folded; exact power of two)
    const float* Qbase = Qp + ((long)(b * LL + q0)) * DD + h * HDIM;
#pragma unroll
    for (int it = 0; it < 8; it++) {
        int s = tid + it * 256;
        int r = s >> 4, c4 = (s & 15) << 2;
        float4 qv = *(const float4*)(Qbase + (long)r * DD + c4);
        Qs[r * QSTR + c4 + 0] = f2tf32(qv.x * 0.125f);
        Qs[r * QSTR + c4 + 1] = f2tf32(qv.y * 0.125f);
        Qs[r * QSTR + c4 + 2] = f2tf32(qv.z * 0.125f);
        Qs[r * QSTR + c4 + 3] = f2tf32(qv.w * 0.125f);
    }

    float Of[8][4];
#pragma unroll
    for (int j = 0; j < 8; j++)
#pragma unroll
        for (int c = 0; c < 4; c++) Of[j][c] = 0.f;
    float m0 = -1e30f, m1 = -1e30f, l0 = 0.f, l1 = 0.f;

    const float* Kb = Kp + ((long)(b * LL)) * DD + h * HDIM;
    const float* Vb = Vp + ((long)(b * LL)) * DD + h * HDIM;
    const int*   Mb = mask + (long)b * LL * LL + (long)q0 * LL;

    for (int kt = 0; kt < LL; kt += AK) {
        __syncthreads();  // prev iter's readers of Ks/Vs/Ms are done

        // Stage K [AK][KSTR], V [AK][VSTR] (tf32)
#pragma unroll
        for (int it = 0; it < 4; it++) {
            int s = tid + it * 256;
            int r = s >> 4, c4 = (s & 15) << 2;
            float4 kv = *(const float4*)(Kb + (long)(kt + r) * DD + c4);
            Ks[r * KSTR + c4 + 0] = f2tf32(kv.x);
            Ks[r * KSTR + c4 + 1] = f2tf32(kv.y);
            Ks[r * KSTR + c4 + 2] = f2tf32(kv.z);
            Ks[r * KSTR + c4 + 3] = f2tf32(kv.w);
            float4 vv = *(const float4*)(Vb + (long)(kt + r) * DD + c4);
            Vs[r * VSTR + c4 + 0] = f2tf32(vv.x);
            Vs[r * VSTR + c4 + 1] = f2tf32(vv.y);
            Vs[r * VSTR + c4 + 2] = f2tf32(vv.z);
            Vs[r * VSTR + c4 + 3] = f2tf32(vv.w);
        }
        // Stage mask tile as packed bytes (coalesced int4 loads, STS.32 packs)
#pragma unroll
        for (int it = 0; it < 8; it++) {
            int s = tid + it * 256;
            int r = s >> 4, c4 = (s & 15) << 2;
            int4 mv = *(const int4*)(Mb + (long)r * LL + kt + c4);
            uint32_t pk = (mv.x ? 1u : 0u)
                        | (mv.y ? 0x100u : 0u)
                        | (mv.z ? 0x10000u : 0u)
                        | (mv.w ? 0x1000000u : 0u);
            *(uint32_t*)(Ms + r * MSTRB + c4) = pk;
        }
        __syncthreads();

        // S = Q @ K^T  (warp: 16 rows x 64 keys)
        float sf[8][4];
#pragma unroll
        for (int j = 0; j < 8; j++)
#pragma unroll
            for (int c = 0; c < 4; c++) sf[j][c] = 0.f;

#pragma unroll
        for (int ks = 0; ks < AK; ks += 8) {
            uint32_t a0 = Qs[row0 * QSTR + ks + tg];
            uint32_t a1 = Qs[row1 * QSTR + ks + tg];
            uint32_t a2 = Qs[row0 * QSTR + ks + tg + 4];
            uint32_t a3 = Qs[row1 * QSTR + ks + tg + 4];
#pragma unroll
            for (int j = 0; j < 8; j++) {
                uint32_t b0 = Ks[(8 * j + g) * KSTR + ks + tg];
                uint32_t b1 = Ks[(8 * j + g) * KSTR + ks + tg + 4];
                mma_tf32(sf[j], a0, a1, a2, a3, b0, b1);
            }
        }

        // Mask (byte reads) + online softmax (rows warp-local; quad reduce)
        float mx0 = -1e30f, mx1 = -1e30f;
#pragma unroll
        for (int j = 0; j < 8; j++) {
            int cb = 8 * j + 2 * tg;
            uchar2 mv0 = *(const uchar2*)(Ms + row0 * MSTRB + cb);
            uchar2 mv1 = *(const uchar2*)(Ms + row1 * MSTRB + cb);
            sf[j][0] = mv0.x ? sf[j][0] : -1e30f;
            sf[j][1] = mv0.y ? sf[j][1] : -1e30f;
            sf[j][2] = mv1.x ? sf[j][2] : -1e30f;
            sf[j][3] = mv1.y ? sf[j][3] : -1e30f;
            mx0 = fmaxf(mx0, fmaxf(sf[j][0], sf[j][1]));
            mx1 = fmaxf(mx1, fmaxf(sf[j][2], sf[j][3]));
        }
        mx0 = fmaxf(mx0, __shfl_xor_sync(0xffffffffu, mx0, 1));
        mx0 = fmaxf(mx0, __shfl_xor_sync(0xffffffffu, mx0, 2));
        mx1 = fmaxf(mx1, __shfl_xor_sync(0xffffffffu, mx1, 1));
        mx1 = fmaxf(mx1, __shfl_xor_sync(0xffffffffu, mx1, 2));

        float mn0 = fmaxf(m0, mx0), mn1 = fmaxf(m1, mx1);
        float cr0 = __expf(m0 - mn0), cr1 = __expf(m1 - mn1);
        m0 = mn0; m1 = mn1;

        float ls0 = 0.f, ls1 = 0.f;
#pragma unroll
        for (int j = 0; j < 8; j++) {
            float p0 = __expf(sf[j][0] - mn0);
            float p1 = __expf(sf[j][1] - mn0);
            float p2 = __expf(sf[j][2] - mn1);
            float p3 = __expf(sf[j][3] - mn1);
            ls0 += p0 + p1;
            ls1 += p2 + p3;
            int cb = 8 * j + 2 * tg;
            *(uint2*)&Pu[row0 * PSTR + cb] = make_uint2(f2tf32(p0), f2tf32(p1));
            *(uint2*)&Pu[row1 * PSTR + cb] = make_uint2(f2tf32(p2), f2tf32(p3));
        }
        ls0 += __shfl_xor_sync(0xffffffffu, ls0, 1);
        ls0 += __shfl_xor_sync(0xffffffffu, ls0, 2);
        ls1 += __shfl_xor_sync(0xffffffffu, ls1, 1);
        ls1 += __shfl_xor_sync(0xffffffffu, ls1, 2);
        l0 = l0 * cr0 + ls0;
        l1 = l1 * cr1 + ls1;
#pragma unroll
        for (int j = 0; j < 8; j++) {
            Of[j][0] *= cr0; Of[j][1] *= cr0;
            Of[j][2] *= cr1; Of[j][3] *= cr1;
        }
        __syncwarp();  // P rows are warp-local in write AND read; lane-cross only

        // O += P @ V
#pragma unroll
        for (int ks = 0; ks < AK; ks += 8) {
            uint32_t a0 = Pu[row0 * PSTR + ks + tg];
            uint32_t a1 = Pu[row1 * PSTR + ks + tg];
            uint32_t a2 = Pu[row0 * PSTR + ks + tg + 4];
            uint32_t a3 = Pu[row1 * PSTR + ks + tg + 4];
#pragma unroll
            for (int j = 0; j < 8; j++) {
                uint32_t b0 = Vs[(ks + tg)     * VSTR + 8 * j + g];
                uint32_t b1 = Vs[(ks + tg + 4) * VSTR + 8 * j + g];
                mma_tf32(Of[j], a0, a1, a2, a3, b0, b1);
            }
        }
    }

    // Normalize, store ctx [B, L, H*HD]
    float inv0 = 1.f / l0, inv1 = 1.f / l1;
    float* Ob = Ctx + ((long)(b * LL + q0)) * DD + h * HDIM;
#pragma unroll
    for (int j = 0; j < 8; j++) {
        int c = 8 * j + 2 * tg;
        *(float2*)&Ob[(long)row0 * DD + c] =
            make_float2(Of[j][0] * inv0, Of[j][1] * inv0);
        *(float2*)&Ob[(long)row1 * DD + c] =
            make_float2(Of[j][2] * inv1, Of[j][3] * inv1);
    }
}

// ---------------------------------------------------------------------------
extern "C" void kernel_launch(void* const* d_in, const int* in_sizes, int n_in,
                              void* d_out, int out_size)
{
    const float* q    = (const float*)d_in[0];
    const float* k    = (const float*)d_in[1];
    const float* v    = (const float*)d_in[2];
    const int*   mask = (const int*)  d_in[3];
    const float* WQ   = (const float*)d_in[4];
    const float* bQ   = (const float*)d_in[5];
    const float* WK   = (const float*)d_in[6];
    const float* bK   = (const float*)d_in[7];
    const float* WV   = (const float*)d_in[8];
    const float* bV   = (const float*)d_in[9];
    const float* WO   = (const float*)d_in[10];
    const float* bO   = (const float*)d_in[11];
    float* out = (float*)d_out;

    float *gQ, *gK, *gV, *gC;
    cudaGetSymbolAddress((void**)&gQ, g_Q);
    cudaGetSymbolAddress((void**)&gK, g_K);
    cudaGetSymbolAddress((void**)&gV, g_V);
    cudaGetSymbolAddress((void**)&gC, g_C);

    static int attr_set = 0;
    if (!attr_set) {
        cudaFuncSetAttribute(sgemm_tf32_pipe_kernel,
                             cudaFuncAttributeMaxDynamicSharedMemorySize, GSMEM);
        cudaFuncSetAttribute(attn_tf32_kernel,
                             cudaFuncAttributeMaxDynamicSharedMemorySize, ATT_SMEM);
        attr_set = 1;
    }

    const int M = BB * LL;  // 8192

    GemmArgs gq = {q, WQ, bQ, gQ};
    GemmArgs gk = {k, WK, bK, gK};
    GemmArgs gv = {v, WV, bV, gV};

    sgemm_tf32_pipe_kernel<<<dim3(DD / GBN, M / GBM, 3), 256, GSMEM>>>(
        gq, gk, gv, M, DD, DD);

    attn_tf32_kernel<<<dim3(LL / AQ, BB * HH), 256, ATT_SMEM>>>(
        gQ, gK, gV, mask, gC);

    GemmArgs go = {gC, WO, bO, out};
    sgemm_tf32_pipe_kernel<<<dim3(DD / GBN, M / GBM, 1), 256, GSMEM>>>(
        go, go, go, M, DD, DD);
}

// round 15
// speedup vs baseline: 1.3716x; 1.0199x over previous
#include <cuda_runtime.h>
#include <cstdint>

#define BB 4
#define LL 2048
#define DD 1024
#define HH 16
#define HDIM 64

// Scratch (allocation-free rule: __device__ globals). 4 x 32 MB.
__device__ float g_Q[BB*LL*DD];
__device__ float g_K[BB*LL*DD];
__device__ float g_V[BB*LL*DD];
__device__ float g_C[BB*LL*DD];

__device__ __forceinline__ uint32_t f2tf32(float x) {
    uint32_t u;
    asm("cvt.rna.tf32.f32 %0, %1;" : "=r"(u) : "f"(x));
    return u;
}

__device__ __forceinline__ void mma_tf32(float* c,
    uint32_t a0, uint32_t a1, uint32_t a2, uint32_t a3,
    uint32_t b0, uint32_t b1)
{
    asm volatile(
        "mma.sync.aligned.m16n8k8.row.col.f32.tf32.tf32.f32 "
        "{%0,%1,%2,%3}, {%4,%5,%6,%7}, {%8,%9}, {%0,%1,%2,%3};\n"
        : "+f"(c[0]), "+f"(c[1]), "+f"(c[2]), "+f"(c[3])
        : "r"(a0), "r"(a1), "r"(a2), "r"(a3), "r"(b0), "r"(b1));
}

__device__ __forceinline__ void cpasync16(uint32_t dst, const void* src) {
    asm volatile("cp.async.cg.shared.global [%0], [%1], 16;\n"
                 :: "r"(dst), "l"(src));
}
__device__ __forceinline__ void cp_commit() {
    asm volatile("cp.async.commit_group;\n" ::: "memory");
}
__device__ __forceinline__ void cp_wait1() {
    asm volatile("cp.async.wait_group 1;\n" ::: "memory");
}

// ---------------------------------------------------------------------------
// TF32 tensor-core GEMM with 2-stage cp.async pipeline (unchanged, 339us).
// ---------------------------------------------------------------------------
#define GBM 128
#define GBN 128
#define GBK 32
#define AP 36
#define BP 136
#define GSMEM ((2*GBM*AP + 2*GBK*BP) * 4)   // 71680 B

struct GemmArgs {
    const float* A; const float* W; const float* bias; float* C;
};

__global__ __launch_bounds__(256) void sgemm_tf32_pipe_kernel(
    GemmArgs ga0, GemmArgs ga1, GemmArgs ga2, int M, int N, int K)
{
    extern __shared__ float smemf[];
    float* Asf = smemf;                 // [2][128][AP]
    float* Bsf = smemf + 2 * GBM * AP;  // [2][32][BP]

    GemmArgs ga = (blockIdx.z == 0) ? ga0 : (blockIdx.z == 1) ? ga1 : ga2;
    const float* __restrict__ A    = ga.A;
    const float* __restrict__ W    = ga.W;
    const float* __restrict__ bias = ga.bias;
    float* __restrict__ C          = ga.C;

    int tid  = threadIdx.x;
    int row0 = blockIdx.y * GBM;
    int col0 = blockIdx.x * GBN;

    int lane = tid & 31;
    int wid  = tid >> 5;
    int g    = lane >> 2;
    int tg   = lane & 3;
    int wm0  = (wid >> 2) * 64;
    int wn0  = (wid & 3) * 32;

    int arow = tid >> 3;
    int acol = (tid & 7) << 2;
    int brow = tid >> 5;
    int bcol = (tid & 31) << 2;

    uint32_t aS = (uint32_t)__cvta_generic_to_shared(Asf);
    uint32_t bS = (uint32_t)__cvta_generic_to_shared(Bsf);

    const float* Abase = A + (long)(row0 + arow) * K + acol;
    const float* Wbase = W + (long)brow * N + col0 + bcol;

    float acc[4][4][4];
#pragma unroll
    for (int i = 0; i < 4; i++)
#pragma unroll
        for (int j = 0; j < 4; j++)
#pragma unroll
            for (int c = 0; c < 4; c++) acc[i][j][c] = 0.f;

    const int NIT = 1024 / GBK;  // 32

    {
        uint32_t ad = aS + (uint32_t)(arow * AP + acol) * 4u;
        uint32_t bd = bS + (uint32_t)(brow * BP + bcol) * 4u;
#pragma unroll
        for (int it = 0; it < 4; it++)
            cpasync16(ad + it * 32 * AP * 4, Abase + (long)(32 * it) * K);
#pragma unroll
        for (int it = 0; it < 4; it++)
            cpasync16(bd + it * 8 * BP * 4, Wbase + (long)(8 * it) * N);
        cp_commit();
    }

    for (int itk = 0; itk < NIT; itk++) {
        int buf = itk & 1;
        if (itk + 1 < NIT) {
            int k0n = (itk + 1) * GBK;
            uint32_t ad = aS + (uint32_t)(((buf ^ 1) * GBM + arow) * AP + acol) * 4u;
            uint32_t bd = bS + (uint32_t)(((buf ^ 1) * GBK + brow) * BP + bcol) * 4u;
#pragma unroll
            for (int it = 0; it < 4; it++)
                cpasync16(ad + it * 32 * AP * 4, Abase + (long)(32 * it) * K + k0n);
#pragma unroll
            for (int it = 0; it < 4; it++)
                cpasync16(bd + it * 8 * BP * 4, Wbase + (long)(k0n + 8 * it) * N);
        }
        cp_commit();
        cp_wait1();
        __syncthreads();

        const float* Ab = Asf + buf * GBM * AP;
        const float* Bb = Bsf + buf * GBK * BP;

#pragma unroll
        for (int ks = 0; ks < GBK; ks += 8) {
            uint32_t af[4][4], bf[4][2];
#pragma unroll
            for (int i = 0; i < 4; i++) {
                int m = wm0 + 16 * i;
                af[i][0] = f2tf32(Ab[(m + g)     * AP + ks + tg]);
                af[i][1] = f2tf32(Ab[(m + g + 8) * AP + ks + tg]);
                af[i][2] = f2tf32(Ab[(m + g)     * AP + ks + tg + 4]);
                af[i][3] = f2tf32(Ab[(m + g + 8) * AP + ks + tg + 4]);
            }
#pragma unroll
            for (int j = 0; j < 4; j++) {
                int n = wn0 + 8 * j;
                bf[j][0] = f2tf32(Bb[(ks + tg)     * BP + n + g]);
                bf[j][1] = f2tf32(Bb[(ks + tg + 4) * BP + n + g]);
            }
#pragma unroll
            for (int i = 0; i < 4; i++)
#pragma unroll
                for (int j = 0; j < 4; j++)
                    mma_tf32(acc[i][j], af[i][0], af[i][1], af[i][2], af[i][3],
                             bf[j][0], bf[j][1]);
        }
        __syncthreads();
    }

#pragma unroll
    for (int i = 0; i < 4; i++) {
        int r = row0 + wm0 + 16 * i + g;
#pragma unroll
        for (int j = 0; j < 4; j++) {
            int c = col0 + wn0 + 8 * j + 2 * tg;
            float b0 = bias[c], b1 = bias[c + 1];
            float2 o0 = make_float2(acc[i][j][0] + b0, acc[i][j][1] + b1);
            float2 o1 = make_float2(acc[i][j][2] + b0, acc[i][j][3] + b1);
            *(float2*)&C[(long)r * N + c]       = o0;
            *(float2*)&C[(long)(r + 8) * N + c] = o1;
        }
    }
}

// ---------------------------------------------------------------------------
// TF32 tensor-core flash attention v3: 128 threads = 4 warps, each warp owns
// 32 query rows (rows [32w, 32w+32)). Same smem layouts/strides as R13.
// Halves cross-warp replication of K/V fragment reads (crossbar-bound fix).
// ---------------------------------------------------------------------------
#define AQ 128
#define AK 64
#define QSTR 68
#define KSTR 68
#define VSTR 72
#define PSTR 68
#define MSTRB 68
#define ATT_SMEM ((AQ*QSTR + AK*KSTR + AK*VSTR + AQ*PSTR) * 4 + AQ*MSTRB)

__global__ __launch_bounds__(128) void attn_tf32_kernel(
    const float* __restrict__ Qp, const float* __restrict__ Kp,
    const float* __restrict__ Vp, const int* __restrict__ mask,
    float* __restrict__ Ctx)
{
    extern __shared__ char smemraw[];
    uint32_t* Qs = (uint32_t*)smemraw;           // [AQ][QSTR] tf32
    uint32_t* Ks = Qs + AQ * QSTR;               // [AK][KSTR] tf32
    uint32_t* Vs = Ks + AK * KSTR;               // [AK][VSTR] tf32
    uint32_t* Pu = Vs + AK * VSTR;               // [AQ][PSTR] P tf32 bits
    unsigned char* Ms = (unsigned char*)(Pu + AQ * PSTR);  // [AQ][MSTRB]

    int tid  = threadIdx.x;
    int lane = tid & 31, wid = tid >> 5;         // wid 0..3
    int g = lane >> 2, tg = lane & 3;
    int wm = wid * 32;
    int bh = blockIdx.y;
    int b = bh / HH, h = bh % HH;
    int q0 = blockIdx.x * AQ;

    int r0 = wm + g;          // four owned row slots
    int r1 = wm + g + 8;
    int r2 = wm + g + 16;
    int r3 = wm + g + 24;

    // Stage Q once (scale folded; 2048 slots / 128 threads = 16 iters)
    const float* Qbase = Qp + ((long)(b * LL + q0)) * DD + h * HDIM;
#pragma unroll
    for (int it = 0; it < 16; it++) {
        int s = tid + it * 128;
        int r = s >> 4, c4 = (s & 15) << 2;
        float4 qv = *(const float4*)(Qbase + (long)r * DD + c4);
        Qs[r * QSTR + c4 + 0] = f2tf32(qv.x * 0.125f);
        Qs[r * QSTR + c4 + 1] = f2tf32(qv.y * 0.125f);
        Qs[r * QSTR + c4 + 2] = f2tf32(qv.z * 0.125f);
        Qs[r * QSTR + c4 + 3] = f2tf32(qv.w * 0.125f);
    }

    float OfA[8][4], OfB[8][4];
#pragma unroll
    for (int j = 0; j < 8; j++)
#pragma unroll
        for (int c = 0; c < 4; c++) { OfA[j][c] = 0.f; OfB[j][c] = 0.f; }
    float m0 = -1e30f, m1 = -1e30f, m2 = -1e30f, m3 = -1e30f;
    float l0 = 0.f, l1 = 0.f, l2 = 0.f, l3 = 0.f;

    const float* Kb = Kp + ((long)(b * LL)) * DD + h * HDIM;
    const float* Vb = Vp + ((long)(b * LL)) * DD + h * HDIM;
    const int*   Mb = mask + (long)b * LL * LL + (long)q0 * LL;

    for (int kt = 0; kt < LL; kt += AK) {
        __syncthreads();  // prev iter's readers of Ks/Vs/Ms done

        // Stage K/V (1024 slots / 128 threads = 8 iters)
#pragma unroll
        for (int it = 0; it < 8; it++) {
            int s = tid + it * 128;
            int r = s >> 4, c4 = (s & 15) << 2;
            float4 kv = *(const float4*)(Kb + (long)(kt + r) * DD + c4);
            Ks[r * KSTR + c4 + 0] = f2tf32(kv.x);
            Ks[r * KSTR + c4 + 1] = f2tf32(kv.y);
            Ks[r * KSTR + c4 + 2] = f2tf32(kv.z);
            Ks[r * KSTR + c4 + 3] = f2tf32(kv.w);
            float4 vv = *(const float4*)(Vb + (long)(kt + r) * DD + c4);
            Vs[r * VSTR + c4 + 0] = f2tf32(vv.x);
            Vs[r * VSTR + c4 + 1] = f2tf32(vv.y);
            Vs[r * VSTR + c4 + 2] = f2tf32(vv.z);
            Vs[r * VSTR + c4 + 3] = f2tf32(vv.w);
        }
        // Stage mask bytes (2048 slots / 128 = 16 iters)
#pragma unroll
        for (int it = 0; it < 16; it++) {
            int s = tid + it * 128;
            int r = s >> 4, c4 = (s & 15) << 2;
            int4 mv = *(const int4*)(Mb + (long)r * LL + kt + c4);
            uint32_t pk = (mv.x ? 1u : 0u)
                        | (mv.y ? 0x100u : 0u)
                        | (mv.z ? 0x10000u : 0u)
                        | (mv.w ? 0x1000000u : 0u);
            *(uint32_t*)(Ms + r * MSTRB + c4) = pk;
        }
        __syncthreads();

        // S = Q @ K^T  (warp: 32 rows x 64 keys, two 16-row groups A/B)
        float sfA[8][4], sfB[8][4];
#pragma unroll
        for (int j = 0; j < 8; j++)
#pragma unroll
            for (int c = 0; c < 4; c++) { sfA[j][c] = 0.f; sfB[j][c] = 0.f; }

#pragma unroll
        for (int ks = 0; ks < AK; ks += 8) {
            uint32_t a0 = Qs[r0 * QSTR + ks + tg];
            uint32_t a1 = Qs[r1 * QSTR + ks + tg];
            uint32_t a2 = Qs[r0 * QSTR + ks + tg + 4];
            uint32_t a3 = Qs[r1 * QSTR + ks + tg + 4];
            uint32_t c0 = Qs[r2 * QSTR + ks + tg];
            uint32_t c1 = Qs[r3 * QSTR + ks + tg];
            uint32_t c2 = Qs[r2 * QSTR + ks + tg + 4];
            uint32_t c3 = Qs[r3 * QSTR + ks + tg + 4];
#pragma unroll
            for (int j = 0; j < 8; j++) {
                uint32_t b0 = Ks[(8 * j + g) * KSTR + ks + tg];
                uint32_t b1 = Ks[(8 * j + g) * KSTR + ks + tg + 4];
                mma_tf32(sfA[j], a0, a1, a2, a3, b0, b1);
                mma_tf32(sfB[j], c0, c1, c2, c3, b0, b1);
            }
        }

        // Mask + online softmax for 4 owned row slots
        float mx0 = -1e30f, mx1 = -1e30f, mx2 = -1e30f, mx3 = -1e30f;
#pragma unroll
        for (int j = 0; j < 8; j++) {
            int cb = 8 * j + 2 * tg;
            uchar2 v0 = *(const uchar2*)(Ms + r0 * MSTRB + cb);
            uchar2 v1 = *(const uchar2*)(Ms + r1 * MSTRB + cb);
            uchar2 v2 = *(const uchar2*)(Ms + r2 * MSTRB + cb);
            uchar2 v3 = *(const uchar2*)(Ms + r3 * MSTRB + cb);
            sfA[j][0] = v0.x ? sfA[j][0] : -1e30f;
            sfA[j][1] = v0.y ? sfA[j][1] : -1e30f;
            sfA[j][2] = v1.x ? sfA[j][2] : -1e30f;
            sfA[j][3] = v1.y ? sfA[j][3] : -1e30f;
            sfB[j][0] = v2.x ? sfB[j][0] : -1e30f;
            sfB[j][1] = v2.y ? sfB[j][1] : -1e30f;
            sfB[j][2] = v3.x ? sfB[j][2] : -1e30f;
            sfB[j][3] = v3.y ? sfB[j][3] : -1e30f;
            mx0 = fmaxf(mx0, fmaxf(sfA[j][0], sfA[j][1]));
            mx1 = fmaxf(mx1, fmaxf(sfA[j][2], sfA[j][3]));
            mx2 = fmaxf(mx2, fmaxf(sfB[j][0], sfB[j][1]));
            mx3 = fmaxf(mx3, fmaxf(sfB[j][2], sfB[j][3]));
        }
#pragma unroll
        for (int off = 1; off <= 2; off <<= 1) {
            mx0 = fmaxf(mx0, __shfl_xor_sync(0xffffffffu, mx0, off));
            mx1 = fmaxf(mx1, __shfl_xor_sync(0xffffffffu, mx1, off));
            mx2 = fmaxf(mx2, __shfl_xor_sync(0xffffffffu, mx2, off));
            mx3 = fmaxf(mx3, __shfl_xor_sync(0xffffffffu, mx3, off));
        }

        float mn0 = fmaxf(m0, mx0), mn1 = fmaxf(m1, mx1);
        float mn2 = fmaxf(m2, mx2), mn3 = fmaxf(m3, mx3);
        float cr0 = __expf(m0 - mn0), cr1 = __expf(m1 - mn1);
        float cr2 = __expf(m2 - mn2), cr3 = __expf(m3 - mn3);
        m0 = mn0; m1 = mn1; m2 = mn2; m3 = mn3;

        float ls0 = 0.f, ls1 = 0.f, ls2 = 0.f, ls3 = 0.f;
#pragma unroll
        for (int j = 0; j < 8; j++) {
            int cb = 8 * j + 2 * tg;
            float p0 = __expf(sfA[j][0] - mn0);
            float p1 = __expf(sfA[j][1] - mn0);
            float p2 = __expf(sfA[j][2] - mn1);
            float p3 = __expf(sfA[j][3] - mn1);
            ls0 += p0 + p1; ls1 += p2 + p3;
            *(uint2*)&Pu[r0 * PSTR + cb] = make_uint2(f2tf32(p0), f2tf32(p1));
            *(uint2*)&Pu[r1 * PSTR + cb] = make_uint2(f2tf32(p2), f2tf32(p3));
            float q0e = __expf(sfB[j][0] - mn2);
            float q1e = __expf(sfB[j][1] - mn2);
            float q2e = __expf(sfB[j][2] - mn3);
            float q3e = __expf(sfB[j][3] - mn3);
            ls2 += q0e + q1e; ls3 += q2e + q3e;
            *(uint2*)&Pu[r2 * PSTR + cb] = make_uint2(f2tf32(q0e), f2tf32(q1e));
            *(uint2*)&Pu[r3 * PSTR + cb] = make_uint2(f2tf32(q2e), f2tf32(q3e));
        }
#pragma unroll
        for (int off = 1; off <= 2; off <<= 1) {
            ls0 += __shfl_xor_sync(0xffffffffu, ls0, off);
            ls1 += __shfl_xor_sync(0xffffffffu, ls1, off);
            ls2 += __shfl_xor_sync(0xffffffffu, ls2, off);
            ls3 += __shfl_xor_sync(0xffffffffu, ls3, off);
        }
        l0 = l0 * cr0 + ls0; l1 = l1 * cr1 + ls1;
        l2 = l2 * cr2 + ls2; l3 = l3 * cr3 + ls3;
#pragma unroll
        for (int j = 0; j < 8; j++) {
            OfA[j][0] *= cr0; OfA[j][1] *= cr0;
            OfA[j][2] *= cr1; OfA[j][3] *= cr1;
            OfB[j][0] *= cr2; OfB[j][1] *= cr2;
            OfB[j][2] *= cr3; OfB[j][3] *= cr3;
        }
        __syncwarp();  // P rows warp-local in write AND read

        // O += P @ V
#pragma unroll
        for (int ks = 0; ks < AK; ks += 8) {
            uint32_t a0 = Pu[r0 * PSTR + ks + tg];
            uint32_t a1 = Pu[r1 * PSTR + ks + tg];
            uint32_t a2 = Pu[r0 * PSTR + ks + tg + 4];
            uint32_t a3 = Pu[r1 * PSTR + ks + tg + 4];
            uint32_t c0 = Pu[r2 * PSTR + ks + tg];
            uint32_t c1 = Pu[r3 * PSTR + ks + tg];
            uint32_t c2 = Pu[r2 * PSTR + ks + tg + 4];
            uint32_t c3 = Pu[r3 * PSTR + ks + tg + 4];
#pragma unroll
            for (int j = 0; j < 8; j++) {
                uint32_t b0 = Vs[(ks + tg)     * VSTR + 8 * j + g];
                uint32_t b1 = Vs[(ks + tg + 4) * VSTR + 8 * j + g];
                mma_tf32(OfA[j], a0, a1, a2, a3, b0, b1);
                mma_tf32(OfB[j], c0, c1, c2, c3, b0, b1);
            }
        }
    }

    // Normalize, store ctx [B, L, H*HD]
    float i0 = 1.f / l0, i1 = 1.f / l1, i2 = 1.f / l2, i3 = 1.f / l3;
    float* Ob = Ctx + ((long)(b * LL + q0)) * DD + h * HDIM;
#pragma unroll
    for (int j = 0; j < 8; j++) {
        int c = 8 * j + 2 * tg;
        *(float2*)&Ob[(long)r0 * DD + c] = make_float2(OfA[j][0] * i0, OfA[j][1] * i0);
        *(float2*)&Ob[(long)r1 * DD + c] = make_float2(OfA[j][2] * i1, OfA[j][3] * i1);
        *(float2*)&Ob[(long)r2 * DD + c] = make_float2(OfB[j][0] * i2, OfB[j][1] * i2);
        *(float2*)&Ob[(long)r3 * DD + c] = make_float2(OfB[j][2] * i3, OfB[j][3] * i3);
    }
}

// ---------------------------------------------------------------------------
extern "C" void kernel_launch(void* const* d_in, const int* in_sizes, int n_in,
                              void* d_out, int out_size)
{
    const float* q    = (const float*)d_in[0];
    const float* k    = (const float*)d_in[1];
    const float* v    = (const float*)d_in[2];
    const int*   mask = (const int*)  d_in[3];
    const float* WQ   = (const float*)d_in[4];
    const float* bQ   = (const float*)d_in[5];
    const float* WK   = (const float*)d_in[6];
    const float* bK   = (const float*)d_in[7];
    const float* WV   = (const float*)d_in[8];
    const float* bV   = (const float*)d_in[9];
    const float* WO   = (const float*)d_in[10];
    const float* bO   = (const float*)d_in[11];
    float* out = (float*)d_out;

    float *gQ, *gK, *gV, *gC;
    cudaGetSymbolAddress((void**)&gQ, g_Q);
    cudaGetSymbolAddress((void**)&gK, g_K);
    cudaGetSymbolAddress((void**)&gV, g_V);
    cudaGetSymbolAddress((void**)&gC, g_C);

    static int attr_set = 0;
    if (!attr_set) {
        cudaFuncSetAttribute(sgemm_tf32_pipe_kernel,
                             cudaFuncAttributeMaxDynamicSharedMemorySize, GSMEM);
        cudaFuncSetAttribute(attn_tf32_kernel,
                             cudaFuncAttributeMaxDynamicSharedMemorySize, ATT_SMEM);
        attr_set = 1;
    }

    const int M = BB * LL;  // 8192

    GemmArgs gq = {q, WQ, bQ, gQ};
    GemmArgs gk = {k, WK, bK, gK};
    GemmArgs gv = {v, WV, bV, gV};

    sgemm_tf32_pipe_kernel<<<dim3(DD / GBN, M / GBM, 3), 256, GSMEM>>>(
        gq, gk, gv, M, DD, DD);

    attn_tf32_kernel<<<dim3(LL / AQ, BB * HH), 128, ATT_SMEM>>>(
        gQ, gK, gV, mask, gC);

    GemmArgs go = {gC, WO, bO, out};
    sgemm_tf32_pipe_kernel<<<dim3(DD / GBN, M / GBM, 1), 256, GSMEM>>>(
        go, go, go, M, DD, DD);
}

// round 16
// speedup vs baseline: 1.4125x; 1.0299x over previous
#include <cuda_runtime.h>
#include <cstdint>

#define BB 4
#define LL 2048
#define DD 1024
#define HH 16
#define HDIM 64

// Scratch (allocation-free rule: __device__ globals). 4 x 32 MB.
__device__ float g_Q[BB*LL*DD];
__device__ float g_K[BB*LL*DD];
__device__ float g_V[BB*LL*DD];
__device__ float g_C[BB*LL*DD];

__device__ __forceinline__ uint32_t f2tf32(float x) {
    uint32_t u;
    asm("cvt.rna.tf32.f32 %0, %1;" : "=r"(u) : "f"(x));
    return u;
}

__device__ __forceinline__ void mma_tf32(float* c,
    uint32_t a0, uint32_t a1, uint32_t a2, uint32_t a3,
    uint32_t b0, uint32_t b1)
{
    asm volatile(
        "mma.sync.aligned.m16n8k8.row.col.f32.tf32.tf32.f32 "
        "{%0,%1,%2,%3}, {%4,%5,%6,%7}, {%8,%9}, {%0,%1,%2,%3};\n"
        : "+f"(c[0]), "+f"(c[1]), "+f"(c[2]), "+f"(c[3])
        : "r"(a0), "r"(a1), "r"(a2), "r"(a3), "r"(b0), "r"(b1));
}

__device__ __forceinline__ void cpasync16(uint32_t dst, const void* src) {
    asm volatile("cp.async.cg.shared.global [%0], [%1], 16;\n"
                 :: "r"(dst), "l"(src));
}
__device__ __forceinline__ void cp_commit() {
    asm volatile("cp.async.commit_group;\n" ::: "memory");
}
__device__ __forceinline__ void cp_wait1() {
    asm volatile("cp.async.wait_group 1;\n" ::: "memory");
}

// ---------------------------------------------------------------------------
// TF32 tensor-core GEMM, 2-stage cp.async pipeline, v2:
// 128 threads = 4 warps; warp tile 64x64 (2x2 warp grid over 128x128 tile).
// Halves LDS+CVT per MMA vs the 8-warp/64x32 version (issue-mix fix).
// Per-element K accumulation order unchanged -> bit-identical results.
// ---------------------------------------------------------------------------
#define GBM 128
#define GBN 128
#define GBK 32
#define AP 36
#define BP 136
#define GSMEM ((2*GBM*AP + 2*GBK*BP) * 4)   // 71680 B

struct GemmArgs {
    const float* A; const float* W; const float* bias; float* C;
};

__global__ __launch_bounds__(128) void sgemm_tf32_pipe_kernel(
    GemmArgs ga0, GemmArgs ga1, GemmArgs ga2, int M, int N, int K)
{
    extern __shared__ float smemf[];
    float* Asf = smemf;                 // [2][128][AP]
    float* Bsf = smemf + 2 * GBM * AP;  // [2][32][BP]

    GemmArgs ga = (blockIdx.z == 0) ? ga0 : (blockIdx.z == 1) ? ga1 : ga2;
    const float* __restrict__ A    = ga.A;
    const float* __restrict__ W    = ga.W;
    const float* __restrict__ bias = ga.bias;
    float* __restrict__ C          = ga.C;

    int tid  = threadIdx.x;
    int row0 = blockIdx.y * GBM;
    int col0 = blockIdx.x * GBN;

    int lane = tid & 31;
    int wid  = tid >> 5;          // 0..3
    int g    = lane >> 2;
    int tg   = lane & 3;
    int wm0  = (wid >> 1) * 64;   // warp m origin
    int wn0  = (wid & 1) * 64;    // warp n origin

    // staging coords (128 threads)
    int arow = tid >> 3;          // 0..15 (+16*it)
    int acol = (tid & 7) << 2;    // 0..28
    int brow = tid >> 5;          // 0..3  (+4*it)
    int bcol = (tid & 31) << 2;   // 0..124

    uint32_t aS = (uint32_t)__cvta_generic_to_shared(Asf);
    uint32_t bS = (uint32_t)__cvta_generic_to_shared(Bsf);

    const float* Abase = A + (long)(row0 + arow) * K + acol;
    const float* Wbase = W + (long)brow * N + col0 + bcol;

    float acc[4][8][4];
#pragma unroll
    for (int i = 0; i < 4; i++)
#pragma unroll
        for (int j = 0; j < 8; j++)
#pragma unroll
            for (int c = 0; c < 4; c++) acc[i][j][c] = 0.f;

    const int NIT = 1024 / GBK;  // 32

    // prologue: stage tile 0 into buf 0
    {
        uint32_t ad = aS + (uint32_t)(arow * AP + acol) * 4u;
        uint32_t bd = bS + (uint32_t)(brow * BP + bcol) * 4u;
#pragma unroll
        for (int it = 0; it < 8; it++)
            cpasync16(ad + it * 16 * AP * 4, Abase + (long)(16 * it) * K);
#pragma unroll
        for (int it = 0; it < 8; it++)
            cpasync16(bd + it * 4 * BP * 4, Wbase + (long)(4 * it) * N);
        cp_commit();
    }

    for (int itk = 0; itk < NIT; itk++) {
        int buf = itk & 1;
        if (itk + 1 < NIT) {
            int k0n = (itk + 1) * GBK;
            uint32_t ad = aS + (uint32_t)(((buf ^ 1) * GBM + arow) * AP + acol) * 4u;
            uint32_t bd = bS + (uint32_t)(((buf ^ 1) * GBK + brow) * BP + bcol) * 4u;
#pragma unroll
            for (int it = 0; it < 8; it++)
                cpasync16(ad + it * 16 * AP * 4, Abase + (long)(16 * it) * K + k0n);
#pragma unroll
            for (int it = 0; it < 8; it++)
                cpasync16(bd + it * 4 * BP * 4, Wbase + (long)(k0n + 4 * it) * N);
        }
        cp_commit();
        cp_wait1();
        __syncthreads();

        const float* Ab = Asf + buf * GBM * AP;
        const float* Bb = Bsf + buf * GBK * BP;

#pragma unroll
        for (int ks = 0; ks < GBK; ks += 8) {
            uint32_t af[4][4], bf[8][2];
#pragma unroll
            for (int i = 0; i < 4; i++) {
                int m = wm0 + 16 * i;
                af[i][0] = f2tf32(Ab[(m + g)     * AP + ks + tg]);
                af[i][1] = f2tf32(Ab[(m + g + 8) * AP + ks + tg]);
                af[i][2] = f2tf32(Ab[(m + g)     * AP + ks + tg + 4]);
                af[i][3] = f2tf32(Ab[(m + g + 8) * AP + ks + tg + 4]);
            }
#pragma unroll
            for (int j = 0; j < 8; j++) {
                int n = wn0 + 8 * j;
                bf[j][0] = f2tf32(Bb[(ks + tg)     * BP + n + g]);
                bf[j][1] = f2tf32(Bb[(ks + tg + 4) * BP + n + g]);
            }
#pragma unroll
            for (int i = 0; i < 4; i++)
#pragma unroll
                for (int j = 0; j < 8; j++)
                    mma_tf32(acc[i][j], af[i][0], af[i][1], af[i][2], af[i][3],
                             bf[j][0], bf[j][1]);
        }
        __syncthreads();
    }

    // Epilogue
#pragma unroll
    for (int i = 0; i < 4; i++) {
        int r = row0 + wm0 + 16 * i + g;
#pragma unroll
        for (int j = 0; j < 8; j++) {
            int c = col0 + wn0 + 8 * j + 2 * tg;
            float b0 = bias[c], b1 = bias[c + 1];
            float2 o0 = make_float2(acc[i][j][0] + b0, acc[i][j][1] + b1);
            float2 o1 = make_float2(acc[i][j][2] + b0, acc[i][j][3] + b1);
            *(float2*)&C[(long)r * N + c]       = o0;
            *(float2*)&C[(long)(r + 8) * N + c] = o1;
        }
    }
}

// ---------------------------------------------------------------------------
// TF32 tensor-core flash attention v3 (unchanged from passing R15 kernel):
// 128 threads = 4 warps, each warp owns 32 query rows.
// ---------------------------------------------------------------------------
#define AQ 128
#define AK 64
#define QSTR 68
#define KSTR 68
#define VSTR 72
#define PSTR 68
#define MSTRB 68
#define ATT_SMEM ((AQ*QSTR + AK*KSTR + AK*VSTR + AQ*PSTR) * 4 + AQ*MSTRB)

__global__ __launch_bounds__(128) void attn_tf32_kernel(
    const float* __restrict__ Qp, const float* __restrict__ Kp,
    const float* __restrict__ Vp, const int* __restrict__ mask,
    float* __restrict__ Ctx)
{
    extern __shared__ char smemraw[];
    uint32_t* Qs = (uint32_t*)smemraw;           // [AQ][QSTR] tf32
    uint32_t* Ks = Qs + AQ * QSTR;               // [AK][KSTR] tf32
    uint32_t* Vs = Ks + AK * KSTR;               // [AK][VSTR] tf32
    uint32_t* Pu = Vs + AK * VSTR;               // [AQ][PSTR] P tf32 bits
    unsigned char* Ms = (unsigned char*)(Pu + AQ * PSTR);  // [AQ][MSTRB]

    int tid  = threadIdx.x;
    int lane = tid & 31, wid = tid >> 5;         // wid 0..3
    int g = lane >> 2, tg = lane & 3;
    int wm = wid * 32;
    int bh = blockIdx.y;
    int b = bh / HH, h = bh % HH;
    int q0 = blockIdx.x * AQ;

    int r0 = wm + g;
    int r1 = wm + g + 8;
    int r2 = wm + g + 16;
    int r3 = wm + g + 24;

    const float* Qbase = Qp + ((long)(b * LL + q0)) * DD + h * HDIM;
#pragma unroll
    for (int it = 0; it < 16; it++) {
        int s = tid + it * 128;
        int r = s >> 4, c4 = (s & 15) << 2;
        float4 qv = *(const float4*)(Qbase + (long)r * DD + c4);
        Qs[r * QSTR + c4 + 0] = f2tf32(qv.x * 0.125f);
        Qs[r * QSTR + c4 + 1] = f2tf32(qv.y * 0.125f);
        Qs[r * QSTR + c4 + 2] = f2tf32(qv.z * 0.125f);
        Qs[r * QSTR + c4 + 3] = f2tf32(qv.w * 0.125f);
    }

    float OfA[8][4], OfB[8][4];
#pragma unroll
    for (int j = 0; j < 8; j++)
#pragma unroll
        for (int c = 0; c < 4; c++) { OfA[j][c] = 0.f; OfB[j][c] = 0.f; }
    float m0 = -1e30f, m1 = -1e30f, m2 = -1e30f, m3 = -1e30f;
    float l0 = 0.f, l1 = 0.f, l2 = 0.f, l3 = 0.f;

    const float* Kb = Kp + ((long)(b * LL)) * DD + h * HDIM;
    const float* Vb = Vp + ((long)(b * LL)) * DD + h * HDIM;
    const int*   Mb = mask + (long)b * LL * LL + (long)q0 * LL;

    for (int kt = 0; kt < LL; kt += AK) {
        __syncthreads();

#pragma unroll
        for (int it = 0; it < 8; it++) {
            int s = tid + it * 128;
            int r = s >> 4, c4 = (s & 15) << 2;
            float4 kv = *(const float4*)(Kb + (long)(kt + r) * DD + c4);
            Ks[r * KSTR + c4 + 0] = f2tf32(kv.x);
            Ks[r * KSTR + c4 + 1] = f2tf32(kv.y);
            Ks[r * KSTR + c4 + 2] = f2tf32(kv.z);
            Ks[r * KSTR + c4 + 3] = f2tf32(kv.w);
            float4 vv = *(const float4*)(Vb + (long)(kt + r) * DD + c4);
            Vs[r * VSTR + c4 + 0] = f2tf32(vv.x);
            Vs[r * VSTR + c4 + 1] = f2tf32(vv.y);
            Vs[r * VSTR + c4 + 2] = f2tf32(vv.z);
            Vs[r * VSTR + c4 + 3] = f2tf32(vv.w);
        }
#pragma unroll
        for (int it = 0; it < 16; it++) {
            int s = tid + it * 128;
            int r = s >> 4, c4 = (s & 15) << 2;
            int4 mv = *(const int4*)(Mb + (long)r * LL + kt + c4);
            uint32_t pk = (mv.x ? 1u : 0u)
                        | (mv.y ? 0x100u : 0u)
                        | (mv.z ? 0x10000u : 0u)
                        | (mv.w ? 0x1000000u : 0u);
            *(uint32_t*)(Ms + r * MSTRB + c4) = pk;
        }
        __syncthreads();

        float sfA[8][4], sfB[8][4];
#pragma unroll
        for (int j = 0; j < 8; j++)
#pragma unroll
            for (int c = 0; c < 4; c++) { sfA[j][c] = 0.f; sfB[j][c] = 0.f; }

#pragma unroll
        for (int ks = 0; ks < AK; ks += 8) {
            uint32_t a0 = Qs[r0 * QSTR + ks + tg];
            uint32_t a1 = Qs[r1 * QSTR + ks + tg];
            uint32_t a2 = Qs[r0 * QSTR + ks + tg + 4];
            uint32_t a3 = Qs[r1 * QSTR + ks + tg + 4];
            uint32_t c0 = Qs[r2 * QSTR + ks + tg];
            uint32_t c1 = Qs[r3 * QSTR + ks + tg];
            uint32_t c2 = Qs[r2 * QSTR + ks + tg + 4];
            uint32_t c3 = Qs[r3 * QSTR + ks + tg + 4];
#pragma unroll
            for (int j = 0; j < 8; j++) {
                uint32_t b0 = Ks[(8 * j + g) * KSTR + ks + tg];
                uint32_t b1 = Ks[(8 * j + g) * KSTR + ks + tg + 4];
                mma_tf32(sfA[j], a0, a1, a2, a3, b0, b1);
                mma_tf32(sfB[j], c0, c1, c2, c3, b0, b1);
            }
        }

        float mx0 = -1e30f, mx1 = -1e30f, mx2 = -1e30f, mx3 = -1e30f;
#pragma unroll
        for (int j = 0; j < 8; j++) {
            int cb = 8 * j + 2 * tg;
            uchar2 v0 = *(const uchar2*)(Ms + r0 * MSTRB + cb);
            uchar2 v1 = *(const uchar2*)(Ms + r1 * MSTRB + cb);
            uchar2 v2 = *(const uchar2*)(Ms + r2 * MSTRB + cb);
            uchar2 v3 = *(const uchar2*)(Ms + r3 * MSTRB + cb);
            sfA[j][0] = v0.x ? sfA[j][0] : -1e30f;
            sfA[j][1] = v0.y ? sfA[j][1] : -1e30f;
            sfA[j][2] = v1.x ? sfA[j][2] : -1e30f;
            sfA[j][3] = v1.y ? sfA[j][3] : -1e30f;
            sfB[j][0] = v2.x ? sfB[j][0] : -1e30f;
            sfB[j][1] = v2.y ? sfB[j][1] : -1e30f;
            sfB[j][2] = v3.x ? sfB[j][2] : -1e30f;
            sfB[j][3] = v3.y ? sfB[j][3] : -1e30f;
            mx0 = fmaxf(mx0, fmaxf(sfA[j][0], sfA[j][1]));
            mx1 = fmaxf(mx1, fmaxf(sfA[j][2], sfA[j][3]));
            mx2 = fmaxf(mx2, fmaxf(sfB[j][0], sfB[j][1]));
            mx3 = fmaxf(mx3, fmaxf(sfB[j][2], sfB[j][3]));
        }
#pragma unroll
        for (int off = 1; off <= 2; off <<= 1) {
            mx0 = fmaxf(mx0, __shfl_xor_sync(0xffffffffu, mx0, off));
            mx1 = fmaxf(mx1, __shfl_xor_sync(0xffffffffu, mx1, off));
            mx2 = fmaxf(mx2, __shfl_xor_sync(0xffffffffu, mx2, off));
            mx3 = fmaxf(mx3, __shfl_xor_sync(0xffffffffu, mx3, off));
        }

        float mn0 = fmaxf(m0, mx0), mn1 = fmaxf(m1, mx1);
        float mn2 = fmaxf(m2, mx2), mn3 = fmaxf(m3, mx3);
        float cr0 = __expf(m0 - mn0), cr1 = __expf(m1 - mn1);
        float cr2 = __expf(m2 - mn2), cr3 = __expf(m3 - mn3);
        m0 = mn0; m1 = mn1; m2 = mn2; m3 = mn3;

        float ls0 = 0.f, ls1 = 0.f, ls2 = 0.f, ls3 = 0.f;
#pragma unroll
        for (int j = 0; j < 8; j++) {
            int cb = 8 * j + 2 * tg;
            float p0 = __expf(sfA[j][0] - mn0);
            float p1 = __expf(sfA[j][1] - mn0);
            float p2 = __expf(sfA[j][2] - mn1);
            float p3 = __expf(sfA[j][3] - mn1);
            ls0 += p0 + p1; ls1 += p2 + p3;
            *(uint2*)&Pu[r0 * PSTR + cb] = make_uint2(f2tf32(p0), f2tf32(p1));
            *(uint2*)&Pu[r1 * PSTR + cb] = make_uint2(f2tf32(p2), f2tf32(p3));
            float q0e = __expf(sfB[j][0] - mn2);
            float q1e = __expf(sfB[j][1] - mn2);
            float q2e = __expf(sfB[j][2] - mn3);
            float q3e = __expf(sfB[j][3] - mn3);
            ls2 += q0e + q1e; ls3 += q2e + q3e;
            *(uint2*)&Pu[r2 * PSTR + cb] = make_uint2(f2tf32(q0e), f2tf32(q1e));
            *(uint2*)&Pu[r3 * PSTR + cb] = make_uint2(f2tf32(q2e), f2tf32(q3e));
        }
#pragma unroll
        for (int off = 1; off <= 2; off <<= 1) {
            ls0 += __shfl_xor_sync(0xffffffffu, ls0, off);
            ls1 += __shfl_xor_sync(0xffffffffu, ls1, off);
            ls2 += __shfl_xor_sync(0xffffffffu, ls2, off);
            ls3 += __shfl_xor_sync(0xffffffffu, ls3, off);
        }
        l0 = l0 * cr0 + ls0; l1 = l1 * cr1 + ls1;
        l2 = l2 * cr2 + ls2; l3 = l3 * cr3 + ls3;
#pragma unroll
        for (int j = 0; j < 8; j++) {
            OfA[j][0] *= cr0; OfA[j][1] *= cr0;
            OfA[j][2] *= cr1; OfA[j][3] *= cr1;
            OfB[j][0] *= cr2; OfB[j][1] *= cr2;
            OfB[j][2] *= cr3; OfB[j][3] *= cr3;
        }
        __syncwarp();

#pragma unroll
        for (int ks = 0; ks < AK; ks += 8) {
            uint32_t a0 = Pu[r0 * PSTR + ks + tg];
            uint32_t a1 = Pu[r1 * PSTR + ks + tg];
            uint32_t a2 = Pu[r0 * PSTR + ks + tg + 4];
            uint32_t a3 = Pu[r1 * PSTR + ks + tg + 4];
            uint32_t c0 = Pu[r2 * PSTR + ks + tg];
            uint32_t c1 = Pu[r3 * PSTR + ks + tg];
            uint32_t c2 = Pu[r2 * PSTR + ks + tg + 4];
            uint32_t c3 = Pu[r3 * PSTR + ks + tg + 4];
#pragma unroll
            for (int j = 0; j < 8; j++) {
                uint32_t b0 = Vs[(ks + tg)     * VSTR + 8 * j + g];
                uint32_t b1 = Vs[(ks + tg + 4) * VSTR + 8 * j + g];
                mma_tf32(OfA[j], a0, a1, a2, a3, b0, b1);
                mma_tf32(OfB[j], c0, c1, c2, c3, b0, b1);
            }
        }
    }

    float i0 = 1.f / l0, i1 = 1.f / l1, i2 = 1.f / l2, i3 = 1.f / l3;
    float* Ob = Ctx + ((long)(b * LL + q0)) * DD + h * HDIM;
#pragma unroll
    for (int j = 0; j < 8; j++) {
        int c = 8 * j + 2 * tg;
        *(float2*)&Ob[(long)r0 * DD + c] = make_float2(OfA[j][0] * i0, OfA[j][1] * i0);
        *(float2*)&Ob[(long)r1 * DD + c] = make_float2(OfA[j][2] * i1, OfA[j][3] * i1);
        *(float2*)&Ob[(long)r2 * DD + c] = make_float2(OfB[j][0] * i2, OfB[j][1] * i2);
        *(float2*)&Ob[(long)r3 * DD + c] = make_float2(OfB[j][2] * i3, OfB[j][3] * i3);
    }
}

// ---------------------------------------------------------------------------
extern "C" void kernel_launch(void* const* d_in, const int* in_sizes, int n_in,
                              void* d_out, int out_size)
{
    const float* q    = (const float*)d_in[0];
    const float* k    = (const float*)d_in[1];
    const float* v    = (const float*)d_in[2];
    const int*   mask = (const int*)  d_in[3];
    const float* WQ   = (const float*)d_in[4];
    const float* bQ   = (const float*)d_in[5];
    const float* WK   = (const float*)d_in[6];
    const float* bK   = (const float*)d_in[7];
    const float* WV   = (const float*)d_in[8];
    const float* bV   = (const float*)d_in[9];
    const float* WO   = (const float*)d_in[10];
    const float* bO   = (const float*)d_in[11];
    float* out = (float*)d_out;

    float *gQ, *gK, *gV, *gC;
    cudaGetSymbolAddress((void**)&gQ, g_Q);
    cudaGetSymbolAddress((void**)&gK, g_K);
    cudaGetSymbolAddress((void**)&gV, g_V);
    cudaGetSymbolAddress((void**)&gC, g_C);

    static int attr_set = 0;
    if (!attr_set) {
        cudaFuncSetAttribute(sgemm_tf32_pipe_kernel,
                             cudaFuncAttributeMaxDynamicSharedMemorySize, GSMEM);
        cudaFuncSetAttribute(attn_tf32_kernel,
                             cudaFuncAttributeMaxDynamicSharedMemorySize, ATT_SMEM);
        attr_set = 1;
    }

    const int M = BB * LL;  // 8192

    GemmArgs gq = {q, WQ, bQ, gQ};
    GemmArgs gk = {k, WK, bK, gK};
    GemmArgs gv = {v, WV, bV, gV};

    sgemm_tf32_pipe_kernel<<<dim3(DD / GBN, M / GBM, 3), 128, GSMEM>>>(
        gq, gk, gv, M, DD, DD);

    attn_tf32_kernel<<<dim3(LL / AQ, BB * HH), 128, ATT_SMEM>>>(
        gQ, gK, gV, mask, gC);

    GemmArgs go = {gC, WO, bO, out};
    sgemm_tf32_pipe_kernel<<<dim3(DD / GBN, M / GBM, 1), 128, GSMEM>>>(
        go, go, go, M, DD, DD);
}